// round 6
// baseline (speedup 1.0000x reference)
#include <cuda_runtime.h>
#include <cuda_fp16.h>

#define NBINS 32
#define NDIM 64
#define NCELL 64
#define RMIN (-5.0f)
#define CELL_SCALE 6.4f           /* NCELL / 10 */
#define THREADS 512
#define BLOCKS 296                /* 148 SMs x 2 CTAs: one persistent wave */
#define STRIDE (BLOCKS * THREADS) /* 151552, compile-time */
#define U 8                       /* pipeline batch */

/* smem layout (all [row][dim]: consecutive lanes = consecutive dims = no
   bank conflicts regardless of divergent row index):
   rec  [NBINS][NDIM] float4 {xk, yk, (A',dk) f16x2, (C',D') f16x2}  32768 B
   cell [NCELL][NDIM] float  (bnd|j packed)                          16384 B
   kxf  [NBINS+1][NDIM] float                                         8448 B
   -> 57600 B, 2 CTAs/SM */
#define OFF_CELL 32768
#define OFF_KXF  (32768 + 16384)
#define SMEM_BYTES (OFF_KXF + 8448)

__device__ __forceinline__ float eval1(float v, int j,
                                       const float4* __restrict__ recd,
                                       float hi)
{
    const float4 r = recd[j * NDIM];
    const float u = v - r.x;
    const float2 ab = __half22float2(*(const __half2*)&r.z);  /* A', dk  */
    const float2 cd = __half22float2(*(const __half2*)&r.w);  /* C', D' */
    const float num = u * fmaf(ab.x, u, ab.y);
    const float den = fmaf(u, fmaf(cd.x, u, cd.y), 1.0f);
    const float y = r.y + __fdividef(num, den);
    return (v >= RMIN && v <= hi) ? y : v;
}

__device__ __forceinline__ int bin_of(float v, const float* __restrict__ celld)
{
    int c = __float2int_rd(fmaf(v, CELL_SCALE, -RMIN * CELL_SCALE));
    c = min(max(c, 0), NCELL - 1);
    const int b = __float_as_int(celld[c * NDIM]);
    const int j = (b & 31) + ((v >= __int_as_float(b)) ? 1 : 0);
    return min(j, NBINS - 1);
}

__device__ __forceinline__ void eval_batch(
    const float* __restrict__ xv,
    const float* __restrict__ celld,
    const float4* __restrict__ recd,
    float hi, float* __restrict__ out, int i)
{
    int jj[U];
    #pragma unroll
    for (int u = 0; u < U; ++u) jj[u] = bin_of(xv[u], celld);
    #pragma unroll
    for (int u = 0; u < U; ++u)
        out[i + u * STRIDE] = eval1(xv[u], jj[u], recd, hi);
}

__global__ __launch_bounds__(THREADS, 2) void rqspline_kernel(
    const float* __restrict__ x,
    const float* __restrict__ bw,
    const float* __restrict__ bh,
    const float* __restrict__ ks,
    float* __restrict__ out,
    int total)
{
    extern __shared__ __align__(16) char smem[];
    float4* rec  = (float4*)smem;
    float*  cell = (float*) (smem + OFF_CELL);
    float*  kxf  = (float*) (smem + OFF_KXF);

    const int t = threadIdx.x;
    const int tid = blockIdx.x * THREADS + t;

    /* ---- prefetch batch 0 BEFORE table build: LDGs fly during build ---- */
    float xc[U];
    const bool full0 = (tid + (U - 1) * STRIDE < total);
    if (full0) {
        #pragma unroll
        for (int u = 0; u < U; ++u) xc[u] = __ldg(x + tid + u * STRIDE);
    }

    /* ---- phase 1: per-dim local-basis coefficients (fp32 build) ---- */
    if (t < NDIM) {
        float cx = RMIN, cy = RMIN;
        #pragma unroll
        for (int j = 0; j < NBINS; ++j) {
            const float nx = cx + bw[t * NBINS + j];  /* reference fp32 cumsum */
            const float ny = cy + bh[t * NBINS + j];
            const float wf = nx - cx;
            const float hf = ny - cy;
            const float dk  = (j == 0) ? 1.0f : ks[t * (NBINS - 1) + j - 1];
            const float dk1 = (j == NBINS - 1) ? 1.0f : ks[t * (NBINS - 1) + j];

            const float s = hf / wf;
            const float c = dk + dk1 - 2.0f * s;
            const float Ap = (s - dk) / wf;              /* A' */
            const float Cp = -c / (hf * wf);             /* C' */
            const float Dp = c / hf;                     /* D' */

            float4 r;
            r.x = cx;
            r.y = cy;
            const __half2 h01 = __floats2half2_rn(Ap, dk);
            const __half2 h23 = __floats2half2_rn(Cp, Dp);
            r.z = __uint_as_float(*(const unsigned*)&h01);
            r.w = __uint_as_float(*(const unsigned*)&h23);
            rec[j * NDIM + t] = r;
            kxf[j * NDIM + t] = cx;
            cx = nx; cy = ny;
        }
        kxf[NBINS * NDIM + t] = cx;
    }
    __syncthreads();

    /* ---- phase 2: cell table, boundary float with j packed in low 5 bits */
    for (int e = t; e < NCELL * NDIM; e += THREADS) {
        const int c = e >> 6, d = e & (NDIM - 1);
        const float cs = RMIN + (float)c * (10.0f / NCELL);
        int j = min(c >> 1, NBINS - 1);
        while (j > 0 && kxf[j * NDIM + d] > cs) --j;
        while (j < NBINS - 1 && kxf[(j + 1) * NDIM + d] <= cs) ++j;
        int bits = __float_as_int(kxf[(j + 1) * NDIM + d]);
        bits = (bits & ~31) | j;   /* ~2e-5 boundary shift: harmless, spline
                                      is continuous across knots */
        cell[c * NDIM + d] = __int_as_float(bits);
    }
    __syncthreads();

    /* ---- phase 3: software-pipelined streaming eval ---- */
    const int d = tid & (NDIM - 1);      /* loop-invariant: STRIDE % 64 == 0 */
    const float4* recd  = rec  + d;
    const float*  celld = cell + d;
    const float hi = kxf[NBINS * NDIM + d];

    int i = tid;
    for (; i + (2 * U - 1) * STRIDE < total; i += U * STRIDE) {
        float xn[U];
        #pragma unroll
        for (int u = 0; u < U; ++u)          /* next batch LDGs in flight */
            xn[u] = __ldg(x + i + (U + u) * STRIDE);
        eval_batch(xc, celld, recd, hi, out, i);
        #pragma unroll
        for (int u = 0; u < U; ++u) xc[u] = xn[u];
    }
    if (full0 && i + (U - 1) * STRIDE < total) {
        eval_batch(xc, celld, recd, hi, out, i);
        i += U * STRIDE;
    }
    for (; i < total; i += STRIDE) {
        const float v = __ldg(x + i);
        out[i] = eval1(v, bin_of(v, celld), recd, hi);
    }
}

extern "C" void kernel_launch(void* const* d_in, const int* in_sizes, int n_in,
                              void* d_out, int out_size) {
    const float* x  = (const float*)d_in[0];
    const float* bw = (const float*)d_in[1];
    const float* bh = (const float*)d_in[2];
    const float* ks = (const float*)d_in[3];
    float* out = (float*)d_out;
    const int total = in_sizes[0];

    cudaFuncSetAttribute(rqspline_kernel,
                         cudaFuncAttributeMaxDynamicSharedMemorySize, SMEM_BYTES);
    rqspline_kernel<<<BLOCKS, THREADS, SMEM_BYTES>>>(x, bw, bh, ks, out, total);
}